// round 13
// baseline (speedup 1.0000x reference)
#include <cuda_runtime.h>

#define TOTD 512
#define HIDD 256
#define OUTD 128

// Packed per-quarter partials: g_part[4*k + q] = {sum_of_x2, prod_of_(1-x2)}.
// Quarters of one unit are contiguous (16B-aligned pairs) so the combine
// kernel reads each unit with two LDG.128.
__device__ float2 g_part[1024];

__global__ void __launch_bounds__(128, 8) wavelet_main_kernel(
    const float* __restrict__ h, const float* __restrict__ y, const float* __restrict__ u,
    const float* __restrict__ W1, const float* __restrict__ b1,
    const float* __restrict__ W2, const float* __restrict__ b2,
    const float* __restrict__ Wy, const float* __restrict__ by,
    float* __restrict__ out)
{
    __shared__ float4 s_inp[TOTD / 4];
    // Per-warp deferred partials: [4 warps][32 rows][33 lanes-padded]
    __shared__ float s_part[4][32][33];
    __shared__ float s_rs[4], s_rp[4];   // per-warp (sum, prod) partials

    const int tid = threadIdx.x;
    // Build inp = concat(h[256], y[128], u[128]) in shared: 1 float4 per thread.
    {
        float4 v;
        if (tid < 64)       v = ((const float4*)h)[tid];
        else if (tid < 96)  v = ((const float4*)y)[tid - 64];
        else                v = ((const float4*)u)[tid - 96];
        s_inp[tid] = v;
    }
    __syncthreads();

    const int lane = tid & 31;
    const int w    = tid >> 5;   // warp id 0..3
    const int bx   = blockIdx.x;

    // Input slice for this lane, register-resident (reused across all rows).
    const float4 iv0 = s_inp[lane +  0];
    const float4 iv1 = s_inp[lane + 32];
    const float4 iv2 = s_inp[lane + 64];
    const float4 iv3 = s_inp[lane + 96];

    if (bx < 1024) {
        // Hidden-unit matvecs: block bx handles k = bx/4, rows [(bx&3)*128, +128).
        // Each of 4 warps owns 32 consecutive rows.
        const int kk = bx >> 2;      // 0..255
        const int q  = bx & 3;
        const float* W;
        const float* b;
        if (kk == 0) { W = W1; b = b1; }
        else {
            W = W2 + (size_t)(kk - 1) * TOTD * TOTD;
            b = b2 + (size_t)(kk - 1) * TOTD;
        }
        const int rbase = q * 128 + w * 32;

        // Pure streaming loop: 8 LDG.128 + 64 FFMA + 2 STS per iteration.
        // All 8 loads issue before first consumption; no reductions, no
        // biases, no shuffles inside the loop.
        #pragma unroll 1
        for (int i = 0; i < 16; i++) {
            const int rowA = rbase + 2 * i;
            const float4* WrA = (const float4*)(W + (size_t)rowA * TOTD);
            const float4* WrB = WrA + (TOTD / 4);
            float4 a0 = __ldcs(WrA + lane +  0);
            float4 a1 = __ldcs(WrA + lane + 32);
            float4 a2 = __ldcs(WrA + lane + 64);
            float4 a3 = __ldcs(WrA + lane + 96);
            float4 c0 = __ldcs(WrB + lane +  0);
            float4 c1 = __ldcs(WrB + lane + 32);
            float4 c2 = __ldcs(WrB + lane + 64);
            float4 c3 = __ldcs(WrB + lane + 96);

            // Tree-structured dots to keep dependency depth low.
            float tA0 = a0.x*iv0.x + a0.y*iv0.y + a0.z*iv0.z + a0.w*iv0.w;
            float tA1 = a1.x*iv1.x + a1.y*iv1.y + a1.z*iv1.z + a1.w*iv1.w;
            float tA2 = a2.x*iv2.x + a2.y*iv2.y + a2.z*iv2.z + a2.w*iv2.w;
            float tA3 = a3.x*iv3.x + a3.y*iv3.y + a3.z*iv3.z + a3.w*iv3.w;
            s_part[w][2 * i + 0][lane] = (tA0 + tA1) + (tA2 + tA3);

            float tB0 = c0.x*iv0.x + c0.y*iv0.y + c0.z*iv0.z + c0.w*iv0.w;
            float tB1 = c1.x*iv1.x + c1.y*iv1.y + c1.z*iv1.z + c1.w*iv1.w;
            float tB2 = c2.x*iv2.x + c2.y*iv2.y + c2.z*iv2.z + c2.w*iv2.w;
            float tB3 = c3.x*iv3.x + c3.y*iv3.y + c3.z*iv3.z + c3.w*iv3.w;
            s_part[w][2 * i + 1][lane] = (tB0 + tB1) + (tB2 + tB3);
        }
        __syncwarp();

        // Epilogue: lane l reduces row (rbase + l): 32 conflict-free LDS + bias.
        float acc = 0.0f;
        #pragma unroll
        for (int j = 0; j < 32; j++) acc += s_part[w][lane][j];
        const float hv = acc + b[rbase + lane];
        const float x2 = hv * hv;
        float runs = x2;
        float runp = 1.0f - x2;
        #pragma unroll
        for (int o = 16; o > 0; o >>= 1) {
            runs += __shfl_xor_sync(0xffffffffu, runs, o);
            runp *= __shfl_xor_sync(0xffffffffu, runp, o);
        }
        if (lane == 0) { s_rs[w] = runs; s_rp[w] = runp; }
        __syncthreads();
        if (tid == 0) {
            float s = (s_rs[0] + s_rs[1]) + (s_rs[2] + s_rs[3]);
            float p = (s_rp[0] * s_rp[1]) * (s_rp[2] * s_rp[3]);
            g_part[bx] = make_float2(s, p);   // one 8B store, 16B-pair packed
        }
    } else {
        // y_out blocks: bx in [1024, 1028), 32 rows of Wy each, 8 rows per warp.
        const int rb = (bx - 1024) * 32 + w * 8;
        #pragma unroll
        for (int i = 0; i < 8; i += 2) {
            const int rowA = rb + i;
            const float4* WrA = (const float4*)(Wy + (size_t)rowA * TOTD);
            const float4* WrB = WrA + (TOTD / 4);
            float4 a0 = __ldg(WrA + lane +  0);
            float4 a1 = __ldg(WrA + lane + 32);
            float4 a2 = __ldg(WrA + lane + 64);
            float4 a3 = __ldg(WrA + lane + 96);
            float4 c0 = __ldg(WrB + lane +  0);
            float4 c1 = __ldg(WrB + lane + 32);
            float4 c2 = __ldg(WrB + lane + 64);
            float4 c3 = __ldg(WrB + lane + 96);

            float accA = a0.x*iv0.x + a0.y*iv0.y + a0.z*iv0.z + a0.w*iv0.w;
            float accB = c0.x*iv0.x + c0.y*iv0.y + c0.z*iv0.z + c0.w*iv0.w;
            accA      += a1.x*iv1.x + a1.y*iv1.y + a1.z*iv1.z + a1.w*iv1.w;
            accB      += c1.x*iv1.x + c1.y*iv1.y + c1.z*iv1.z + c1.w*iv1.w;
            accA      += a2.x*iv2.x + a2.y*iv2.y + a2.z*iv2.z + a2.w*iv2.w;
            accB      += c2.x*iv2.x + c2.y*iv2.y + c2.z*iv2.z + c2.w*iv2.w;
            accA      += a3.x*iv3.x + a3.y*iv3.y + a3.z*iv3.z + a3.w*iv3.w;
            accB      += c3.x*iv3.x + c3.y*iv3.y + c3.z*iv3.z + c3.w*iv3.w;

            #pragma unroll
            for (int o = 16; o > 0; o >>= 1) {
                accA += __shfl_xor_sync(0xffffffffu, accA, o);
                accB += __shfl_xor_sync(0xffffffffu, accB, o);
            }
            if (lane == 0) {
                out[HIDD + rowA]     = accA + by[rowA];
                out[HIDD + rowA + 1] = accB + by[rowA + 1];
            }
        }
    }
}

// PDL combine: launch/setup overlaps the main kernel's tail; gridDepSync gates
// the reads. Each thread: 2 independent LDG.128 (the unit's 4 packed partials),
// then combine + expf + 1 store. Latency-bound ~600cyc, not 8 scattered loads.
__global__ void wavelet_combine_kernel(float* __restrict__ out)
{
#if __CUDA_ARCH__ >= 900
    cudaGridDependencySynchronize();
#endif
    const int t = threadIdx.x;   // 0..255 == unit k
    const float4* gp = (const float4*)g_part;   // 2 float2 per float4
    const float4 v0 = __ldcg(gp + 2 * t + 0);   // {s0,p0,s1,p1}
    const float4 v1 = __ldcg(gp + 2 * t + 1);   // {s2,p2,s3,p3}
    const float s = (v0.x + v0.z) + (v1.x + v1.z);
    float a;
    if (t == 0) {
        a = expf(-0.5f * s);   // Gaussian scaling unit
    } else {
        const float p = (v0.y * v0.w) * (v1.y * v1.w);
        a = p * expf(-0.5f * s);   // Mexican-hat product
    }
    out[t] = a;
}

extern "C" void kernel_launch(void* const* d_in, const int* in_sizes, int n_in,
                              void* d_out, int out_size)
{
    const float* h  = (const float*)d_in[0];
    const float* y  = (const float*)d_in[1];
    const float* u  = (const float*)d_in[2];
    const float* W1 = (const float*)d_in[3];
    const float* b1 = (const float*)d_in[4];
    const float* W2 = (const float*)d_in[5];
    const float* b2 = (const float*)d_in[6];
    const float* Wy = (const float*)d_in[7];
    const float* by = (const float*)d_in[8];
    float* out = (float*)d_out;

    wavelet_main_kernel<<<1028, 128>>>(h, y, u, W1, b1, W2, b2, Wy, by, out);

    // Combine with programmatic dependent launch: overlaps launch latency
    // with the main kernel; correctness via cudaGridDependencySynchronize.
    cudaLaunchAttribute attrs[1];
    attrs[0].id = cudaLaunchAttributeProgrammaticStreamSerialization;
    attrs[0].val.programmaticStreamSerializationAllowed = 1;

    cudaLaunchConfig_t cfg = {};
    cfg.gridDim  = dim3(1, 1, 1);
    cfg.blockDim = dim3(256, 1, 1);
    cfg.dynamicSmemBytes = 0;
    cfg.stream   = 0;
    cfg.attrs    = attrs;
    cfg.numAttrs = 1;
    cudaLaunchKernelEx(&cfg, wavelet_combine_kernel, out);
}

// round 14
// speedup vs baseline: 1.0075x; 1.0075x over previous
#include <cuda_runtime.h>

#define TOTD 512
#define HIDD 256
#define OUTD 128

// Packed per-half partials: g_part[2*k + half] = {sum_of_x2, prod_of_(1-x2)}.
// Halves of one unit are contiguous (16B-aligned) so the combining block
// reads each unit with a single LDG.128.
__device__ float2 g_part[512];
__device__ unsigned int g_count = 0;   // self-resetting via atomicInc wrap (511 -> 0)

__global__ void __launch_bounds__(256, 4) wavelet_fused_kernel(
    const float* __restrict__ h, const float* __restrict__ y, const float* __restrict__ u,
    const float* __restrict__ W1, const float* __restrict__ b1,
    const float* __restrict__ W2, const float* __restrict__ b2,
    const float* __restrict__ Wy, const float* __restrict__ by,
    float* __restrict__ out)
{
    __shared__ float4 s_inp[TOTD / 4];
    // Per-warp deferred partials: [8 warps][32 rows][33 lanes-padded]
    __shared__ float s_part[8][32][33];
    __shared__ float s_rs[8], s_rp[8];   // per-warp (sum, prod) partials
    __shared__ bool s_last;

    const int tid = threadIdx.x;
    // Build inp = concat(h[256], y[128], u[128]) in shared: threads 0..127 load.
    if (tid < 128) {
        float4 v;
        if (tid < 64)       v = ((const float4*)h)[tid];
        else if (tid < 96)  v = ((const float4*)y)[tid - 64];
        else                v = ((const float4*)u)[tid - 96];
        s_inp[tid] = v;
    }
    if (tid == 0) s_last = false;
    __syncthreads();

    const int lane = tid & 31;
    const int w    = tid >> 5;   // warp id 0..7
    const int bx   = blockIdx.x;

    // Input slice for this lane, register-resident (reused across all rows).
    const float4 iv0 = s_inp[lane +  0];
    const float4 iv1 = s_inp[lane + 32];
    const float4 iv2 = s_inp[lane + 64];
    const float4 iv3 = s_inp[lane + 96];

    if (bx < 512) {
        // Hidden-unit matvecs: block bx handles k = bx/2, rows [(bx&1)*256, +256).
        // Each of 8 warps owns 32 consecutive rows.
        const int kk   = bx >> 1;      // 0..255
        const int half = bx & 1;
        const float* W;
        const float* b;
        if (kk == 0) { W = W1; b = b1; }
        else {
            W = W2 + (size_t)(kk - 1) * TOTD * TOTD;
            b = b2 + (size_t)(kk - 1) * TOTD;
        }
        const int rbase = half * 256 + w * 32;

        // Pure streaming loop: 8 LDG.128 + 64 FFMA + 2 STS per iteration.
        // All 8 loads issue before first consumption; no reductions, no
        // biases, no shuffles inside the loop.
        #pragma unroll 1
        for (int i = 0; i < 16; i++) {
            const int rowA = rbase + 2 * i;
            const float4* WrA = (const float4*)(W + (size_t)rowA * TOTD);
            const float4* WrB = WrA + (TOTD / 4);
            float4 a0 = __ldcs(WrA + lane +  0);
            float4 a1 = __ldcs(WrA + lane + 32);
            float4 a2 = __ldcs(WrA + lane + 64);
            float4 a3 = __ldcs(WrA + lane + 96);
            float4 c0 = __ldcs(WrB + lane +  0);
            float4 c1 = __ldcs(WrB + lane + 32);
            float4 c2 = __ldcs(WrB + lane + 64);
            float4 c3 = __ldcs(WrB + lane + 96);

            // Tree-structured dots to keep dependency depth low.
            float tA0 = a0.x*iv0.x + a0.y*iv0.y + a0.z*iv0.z + a0.w*iv0.w;
            float tA1 = a1.x*iv1.x + a1.y*iv1.y + a1.z*iv1.z + a1.w*iv1.w;
            float tA2 = a2.x*iv2.x + a2.y*iv2.y + a2.z*iv2.z + a2.w*iv2.w;
            float tA3 = a3.x*iv3.x + a3.y*iv3.y + a3.z*iv3.z + a3.w*iv3.w;
            s_part[w][2 * i + 0][lane] = (tA0 + tA1) + (tA2 + tA3);

            float tB0 = c0.x*iv0.x + c0.y*iv0.y + c0.z*iv0.z + c0.w*iv0.w;
            float tB1 = c1.x*iv1.x + c1.y*iv1.y + c1.z*iv1.z + c1.w*iv1.w;
            float tB2 = c2.x*iv2.x + c2.y*iv2.y + c2.z*iv2.z + c2.w*iv2.w;
            float tB3 = c3.x*iv3.x + c3.y*iv3.y + c3.z*iv3.z + c3.w*iv3.w;
            s_part[w][2 * i + 1][lane] = (tB0 + tB1) + (tB2 + tB3);
        }
        __syncwarp();

        // Epilogue: lane l reduces row (rbase + l): 32 conflict-free LDS + bias.
        float acc = 0.0f;
        #pragma unroll
        for (int j = 0; j < 32; j++) acc += s_part[w][lane][j];
        const float hv = acc + b[rbase + lane];
        const float x2 = hv * hv;
        float runs = x2;
        float runp = 1.0f - x2;
        #pragma unroll
        for (int o = 16; o > 0; o >>= 1) {
            runs += __shfl_xor_sync(0xffffffffu, runs, o);
            runp *= __shfl_xor_sync(0xffffffffu, runp, o);
        }
        if (lane == 0) { s_rs[w] = runs; s_rp[w] = runp; }
        __syncthreads();
        if (tid == 0) {
            float s = ((s_rs[0] + s_rs[1]) + (s_rs[2] + s_rs[3]))
                    + ((s_rs[4] + s_rs[5]) + (s_rs[6] + s_rs[7]));
            float p = ((s_rp[0] * s_rp[1]) * (s_rp[2] * s_rp[3]))
                    * ((s_rp[4] * s_rp[5]) * (s_rp[6] * s_rp[7]));
            g_part[bx] = make_float2(s, p);   // one 8B store, unit-contiguous
            // Publish, then count arrivals. atomicInc wraps 511 -> 0: counter
            // self-resets for the next graph replay. (516x256 atomic-fused
            // launch shape validated clean in R4.)
            __threadfence();
            unsigned int v = atomicInc(&g_count, 511u);
            s_last = (v == 511u);
        }
        __syncthreads();

        if (s_last) {
            // Last-arriving block combines both halves per unit -> out[0..255].
            const int t = tid;   // 0..255 == unit k
            const float4 v = __ldcg((const float4*)g_part + t);  // {s0,p0,s1,p1}
            const float s = v.x + v.z;
            float a;
            if (t == 0) {
                a = expf(-0.5f * s);       // Gaussian scaling unit
            } else {
                a = (v.y * v.w) * expf(-0.5f * s);   // Mexican-hat product
            }
            out[t] = a;
        }
    } else {
        // y_out blocks: bx in [512, 516), 32 rows of Wy each, 4 rows per warp.
        const int rb = (bx - 512) * 32 + w * 4;
        #pragma unroll
        for (int i = 0; i < 4; i += 2) {
            const int rowA = rb + i;
            const float4* WrA = (const float4*)(Wy + (size_t)rowA * TOTD);
            const float4* WrB = WrA + (TOTD / 4);
            float4 a0 = __ldg(WrA + lane +  0);
            float4 a1 = __ldg(WrA + lane + 32);
            float4 a2 = __ldg(WrA + lane + 64);
            float4 a3 = __ldg(WrA + lane + 96);
            float4 c0 = __ldg(WrB + lane +  0);
            float4 c1 = __ldg(WrB + lane + 32);
            float4 c2 = __ldg(WrB + lane + 64);
            float4 c3 = __ldg(WrB + lane + 96);

            float accA = a0.x*iv0.x + a0.y*iv0.y + a0.z*iv0.z + a0.w*iv0.w;
            float accB = c0.x*iv0.x + c0.y*iv0.y + c0.z*iv0.z + c0.w*iv0.w;
            accA      += a1.x*iv1.x + a1.y*iv1.y + a1.z*iv1.z + a1.w*iv1.w;
            accB      += c1.x*iv1.x + c1.y*iv1.y + c1.z*iv1.z + c1.w*iv1.w;
            accA      += a2.x*iv2.x + a2.y*iv2.y + a2.z*iv2.z + a2.w*iv2.w;
            accB      += c2.x*iv2.x + c2.y*iv2.y + c2.z*iv2.z + c2.w*iv2.w;
            accA      += a3.x*iv3.x + a3.y*iv3.y + a3.z*iv3.z + a3.w*iv3.w;
            accB      += c3.x*iv3.x + c3.y*iv3.y + c3.z*iv3.z + c3.w*iv3.w;

            #pragma unroll
            for (int o = 16; o > 0; o >>= 1) {
                accA += __shfl_xor_sync(0xffffffffu, accA, o);
                accB += __shfl_xor_sync(0xffffffffu, accB, o);
            }
            if (lane == 0) {
                out[HIDD + rowA]     = accA + by[rowA];
                out[HIDD + rowA + 1] = accB + by[rowA + 1];
            }
        }
    }
}

extern "C" void kernel_launch(void* const* d_in, const int* in_sizes, int n_in,
                              void* d_out, int out_size)
{
    const float* h  = (const float*)d_in[0];
    const float* y  = (const float*)d_in[1];
    const float* u  = (const float*)d_in[2];
    const float* W1 = (const float*)d_in[3];
    const float* b1 = (const float*)d_in[4];
    const float* W2 = (const float*)d_in[5];
    const float* b2 = (const float*)d_in[6];
    const float* Wy = (const float*)d_in[7];
    const float* by = (const float*)d_in[8];
    float* out = (float*)d_out;

    wavelet_fused_kernel<<<516, 256>>>(h, y, u, W1, b1, W2, b2, Wy, by, out);
}